// round 9
// baseline (speedup 1.0000x reference)
#include <cuda_runtime.h>

#define NS      4
#define NA      8192
#define NC      8
#define THR2    1.21f
#define GRID    40
#define GRIDXY  (GRID * GRID)
#define CELLS   (GRID * GRID * GRID)     // 64000
#define CELLSP  65536                    // padded (power of two) for the scan
#define ORIGIN  (-22.04f)
#define INV_H   (1.0f / 1.102f)          // h = 1.102 > 1.1 clash radius

// Device-global scratch. Replay invariants: g_counts, g_npc, g_cellCounts,
// g_hd, g_sd are zero on entry (zero-init at load; consumers re-zero).
__device__ int g_counts[NS * NC * NC];
__device__ int g_npc[NC];
__device__ int g_hd[NS];                 // hist blocks done per sample
__device__ int g_sd;                     // search blocks done
__device__ __align__(16) int    g_cellCounts[NS][CELLSP];
__device__ __align__(16) int    g_cellStarts[NS][CELLSP + 4];
__device__ int    g_cellrank[NS * NA];   // cell | rank<<16
__device__ int    g_chain[NA];
__device__ __align__(16) float4 g_pk[NS][NA];   // (x,y,z,q) cell-sorted
__device__ int    g_meta[NS][NA];               // chain of sorted atom

__device__ __forceinline__ int cellco(float v) {
    int c = __float2int_rd((v - ORIGIN) * INV_H);
    return min(GRID - 1, max(0, c));
}

// ---------------------------------------------------------------------------
// 1) hist (+ fused per-sample scan in the last-arriving block of each sample).
//    32 blocks x 1024 threads; blocks 8b..8b+7 cover sample b's atoms only.
__global__ __launch_bounds__(1024) void hist_kernel(
    const float* __restrict__ coord,
    const int*   __restrict__ asym,
    const int*   __restrict__ a2t)
{
    __shared__ int s_w[32];
    __shared__ int s_last;

    int tid = threadIdx.x;
    int t   = blockIdx.x * 1024 + tid;
    int s   = t >> 13;

    float x = coord[3 * t], y = coord[3 * t + 1], z = coord[3 * t + 2];
    int cell = cellco(x) + GRID * cellco(y) + GRIDXY * cellco(z);
    int rank = atomicAdd(&g_cellCounts[s][cell], 1);
    g_cellrank[t] = cell | (rank << 16);
    if (t < NA) {
        int ch = asym[a2t[t]];
        g_chain[t] = ch;
        atomicAdd(&g_npc[ch], 1);
    }

    __threadfence();
    __syncthreads();
    if (tid == 0) {
        int r = atomicAdd(&g_hd[s], 1);
        s_last = (r == 7);
        if (r == 7) g_hd[s] = 0;           // reset for next replay
    }
    __syncthreads();
    if (!s_last) return;

    // ---- exclusive scan of sample s's 65536 (padded) cell counts ----
    int lane = tid & 31, wid = tid >> 5;
    int base = tid * 64;
    const int4* mine = (const int4*)(g_cellCounts[s] + base);
    int4 v[16];
    int sum = 0;
#pragma unroll
    for (int k = 0; k < 16; ++k) {
        v[k] = __ldcg(mine + k);           // L2 read: sees other blocks' atomics
        sum += v[k].x + v[k].y + v[k].z + v[k].w;
    }
    int inc = sum;
#pragma unroll
    for (int d = 1; d < 32; d <<= 1) {
        int u = __shfl_up_sync(0xFFFFFFFF, inc, d);
        if (lane >= d) inc += u;
    }
    if (lane == 31) s_w[wid] = inc;
    __syncthreads();
    if (wid == 0) {
        int t0 = s_w[lane];
        int i2 = t0;
#pragma unroll
        for (int d = 1; d < 32; d <<= 1) {
            int u = __shfl_up_sync(0xFFFFFFFF, i2, d);
            if (lane >= d) i2 += u;
        }
        s_w[lane] = i2 - t0;               // exclusive warp offsets
    }
    __syncthreads();
    int run = s_w[wid] + (inc - sum);

    int4* st4 = (int4*)(g_cellStarts[s] + base);
    int4* cc4 = (int4*)(g_cellCounts[s] + base);
#pragma unroll
    for (int k = 0; k < 16; ++k) {
        int4 o;
        o.x = run;           run += v[k].x;
        o.y = run;           run += v[k].y;
        o.z = run;           run += v[k].z;
        o.w = run;           run += v[k].w;
        st4[k] = o;
        cc4[k] = make_int4(0, 0, 0, 0);    // restore replay invariant
    }
}

// ---------------------------------------------------------------------------
// 2) scatter: atomic-free, pos = starts[cell] + rank.
__global__ __launch_bounds__(1024) void scatter_kernel(
    const float* __restrict__ coord)
{
    int t = blockIdx.x * 1024 + threadIdx.x;
    int s = t >> 13;
    int a = t & (NA - 1);
    float x = coord[3 * t], y = coord[3 * t + 1], z = coord[3 * t + 2];
    float q = fmaf(x, x, fmaf(y, y, z * z));
    int cr   = g_cellrank[t];
    int cell = cr & 0xFFFF;
    int rank = cr >> 16;
    int pos  = g_cellStarts[s][cell] + rank;
    g_pk[s][pos]   = make_float4(x, y, z, q);
    g_meta[s][pos] = g_chain[a];
}

// ---------------------------------------------------------------------------
// 3) search: forward half-stencil, thread per (atom, segment). Segments:
//    0..2: rows (z+1, y-1..y+1); 3: row (z, y+1); 4: own row tail j>k.
//    Forward cells have larger linear index, and within the own cell we start
//    at k+1, so each pair is visited exactly once with NO id test. Same fp32
//    predicate association as the accepted brute-force kernel.
//    Last block runs finalize. out: [ has (256) | details (512, (tot,rel)) ]
__global__ __launch_bounds__(256, 8) void search_kernel(float* __restrict__ out) {
    __shared__ int scnt[NC * NC];
    __shared__ int s_last;
    int tid = threadIdx.x;
    if (tid < NC * NC) scnt[tid] = 0;
    __syncthreads();

    int bx  = blockIdx.x;
    int seg = bx >> 7;                     // 0..4
    int t   = ((bx & 127) << 8) | tid;
    int s   = t >> 13;
    int k   = t & (NA - 1);

    float4 p  = g_pk[s][k];
    int    ci = g_meta[s][k];

    float m2x = -2.0f * p.x, m2y = -2.0f * p.y, m2z = -2.0f * p.z;
    float K   = p.w - THR2;

    int cx = cellco(p.x), cy = cellco(p.y), cz = cellco(p.z);
    int x0 = max(cx - 1, 0), x1 = min(cx + 1, GRID - 1);

    const int* st = g_cellStarts[s];
    int lo = 0, hi = 0;
    if (seg < 3) {
        int zz = cz + 1, yy = cy - 1 + seg;
        if (zz < GRID && yy >= 0 && yy < GRID) {
            int row = GRID * yy + GRIDXY * zz;
            lo = st[row + x0];
            hi = st[row + x1 + 1];
        }
    } else if (seg == 3) {
        int yy = cy + 1;
        if (yy < GRID) {
            int row = GRID * yy + GRIDXY * cz;
            lo = st[row + x0];
            hi = st[row + x1 + 1];
        }
    } else {
        int row = GRID * cy + GRIDXY * cz;
        lo = k + 1;                        // own cell tail + forward x cell
        hi = st[row + x1 + 1];
    }

    const float4* pk = g_pk[s];
    const int*    mt = g_meta[s];
    int bucket = ci * NC;

    int j = lo;
    for (; j + 1 < hi; j += 2) {
        float4 a = pk[j];
        float4 c = pk[j + 1];
        int ma = mt[j];
        int mb = mt[j + 1];
        float da = fmaf(m2z, a.z, fmaf(m2y, a.y, fmaf(m2x, a.x, a.w))) + K;
        float db = fmaf(m2z, c.z, fmaf(m2y, c.y, fmaf(m2x, c.x, c.w))) + K;
        if (da < 0.0f && ma != ci) atomicAdd(&scnt[bucket + ma], 1);
        if (db < 0.0f && mb != ci) atomicAdd(&scnt[bucket + mb], 1);
    }
    if (j < hi) {
        float4 a = pk[j];
        int ma = mt[j];
        float da = fmaf(m2z, a.z, fmaf(m2y, a.y, fmaf(m2x, a.x, a.w))) + K;
        if (da < 0.0f && ma != ci) atomicAdd(&scnt[bucket + ma], 1);
    }

    __syncthreads();
    if (tid < NC * NC) {
        int v = scnt[tid];
        if (v) atomicAdd(&g_counts[s * NC * NC + tid], v);
    }
    __threadfence();
    __syncthreads();
    if (tid == 0) {
        int r = atomicAdd(&g_sd, 1);
        s_last = (r == 5 * 128 - 1);
        if (s_last) g_sd = 0;              // reset for next replay
    }
    __syncthreads();
    if (!s_last) return;

    // ---- fused finalize (256 threads -> one (sample, a, b) each) ----
    {
        int fs = tid >> 6;
        int r  = tid & 63;
        int a  = r >> 3;
        int b  = r & 7;

        int tot_i = 0;
        if (a != b)
            tot_i = __ldcg(&g_counts[fs * NC * NC + a * NC + b]) +
                    __ldcg(&g_counts[fs * NC * NC + b * NC + a]);
        float tot = (float)tot_i;
        float mn  = (float)min(__ldcg(&g_npc[a]), __ldcg(&g_npc[b]));
        float rel = tot / mn;
        bool  has = (tot > 100.0f) || (rel > 0.5f);

        out[tid]                        = has ? 1.0f : 0.0f;
        out[NS * NC * NC + 2 * tid]     = tot;
        out[NS * NC * NC + 2 * tid + 1] = rel;

        __syncthreads();                   // all reads done
        g_counts[tid] = 0;                 // reset replay invariants
        if (tid < NC) g_npc[tid] = 0;
    }
}

// ---------------------------------------------------------------------------
extern "C" void kernel_launch(void* const* d_in, const int* in_sizes, int n_in,
                              void* d_out, int out_size) {
    const float* coord = (const float*)d_in[0];   // [S, N, 3] f32
    const int*   asym  = (const int*)  d_in[1];   // [N_TOKENS] i32
    const int*   a2t   = (const int*)  d_in[2];   // [N] i32
    float*       out   = (float*)d_out;

    hist_kernel   <<<32, 1024>>>(coord, asym, a2t);
    scatter_kernel<<<32, 1024>>>(coord);
    search_kernel <<<5 * 128, 256>>>(out);
}

// round 10
// speedup vs baseline: 1.4902x; 1.4902x over previous
#include <cuda_runtime.h>

#define NS      4
#define NA      8192
#define NC      8
#define THR2    1.21f
#define GRID    32
#define GRIDXY  (GRID * GRID)
#define CELLS   (GRID * GRID * GRID)     // 32768
#define ORIGIN  (-17.632f)
#define INV_H   (1.0f / 1.102f)          // h = 1.102 > 1.1 clash radius

// Device-global scratch. Replay invariants: g_counts, g_npc, g_cellCounts,
// g_sd are zero on entry (zero-init at load; consumers re-zero after use).
__device__ int g_counts[NS * NC * NC];
__device__ int g_npc[NC];
__device__ int g_sd;                     // search blocks done
__device__ __align__(16) int    g_cellCounts[NS][CELLS];
__device__ __align__(16) int    g_cellStarts[NS][CELLS + 4];
__device__ int    g_cellrank[NS * NA];   // cell | rank<<16
__device__ int    g_chain[NA];
__device__ __align__(16) float4 g_pk[NS][NA];   // (x,y,z,q) cell-sorted
__device__ int    g_meta[NS][NA];               // chain of sorted atom

__device__ __forceinline__ int cellco(float v) {
    int c = __float2int_rd((v - ORIGIN) * INV_H);
    return min(GRID - 1, max(0, c));
}

// ---------------------------------------------------------------------------
// 1) hist: thread per (sample, atom). The histogram atomic's return value is
//    the atom's rank within its cell. Chain map + npc built once (t < NA).
__global__ __launch_bounds__(256) void hist_kernel(
    const float* __restrict__ coord,
    const int*   __restrict__ asym,
    const int*   __restrict__ a2t)
{
    int t = blockIdx.x * 256 + threadIdx.x;   // 0 .. NS*NA-1
    int s = t >> 13;
    float x = coord[3 * t], y = coord[3 * t + 1], z = coord[3 * t + 2];
    int cell = cellco(x) + GRID * cellco(y) + GRIDXY * cellco(z);
    int rank = atomicAdd(&g_cellCounts[s][cell], 1);
    g_cellrank[t] = cell | (rank << 16);
    if (t < NA) {
        int ch = asym[a2t[t]];
        g_chain[t] = ch;
        atomicAdd(&g_npc[ch], 1);
    }
}

// ---------------------------------------------------------------------------
// 2) scan: one block per sample; warp-shuffle two-level exclusive scan of
//    32768 cell counts (32 per thread, v[8] int4 = no spills). Writes starts
//    and zeroes counts (replay invariant).
__global__ __launch_bounds__(1024, 1) void scan_kernel() {
    __shared__ int s_w[32];
    int s    = blockIdx.x;
    int tid  = threadIdx.x;
    int lane = tid & 31;
    int wid  = tid >> 5;

    int base = tid * 32;
    const int4* mine = (const int4*)(g_cellCounts[s] + base);
    int4 v[8];
    int sum = 0;
#pragma unroll
    for (int k = 0; k < 8; ++k) {
        v[k] = mine[k];
        sum += v[k].x + v[k].y + v[k].z + v[k].w;
    }
    int inc = sum;
#pragma unroll
    for (int d = 1; d < 32; d <<= 1) {
        int u = __shfl_up_sync(0xFFFFFFFF, inc, d);
        if (lane >= d) inc += u;
    }
    if (lane == 31) s_w[wid] = inc;
    __syncthreads();
    if (wid == 0) {
        int t0 = s_w[lane];
        int i2 = t0;
#pragma unroll
        for (int d = 1; d < 32; d <<= 1) {
            int u = __shfl_up_sync(0xFFFFFFFF, i2, d);
            if (lane >= d) i2 += u;
        }
        s_w[lane] = i2 - t0;               // exclusive warp offsets
    }
    __syncthreads();
    int run = s_w[wid] + (inc - sum);      // exclusive start for this thread

    int4* st4 = (int4*)(g_cellStarts[s] + base);
    int4* cc4 = (int4*)(g_cellCounts[s] + base);
#pragma unroll
    for (int k = 0; k < 8; ++k) {
        int4 o;
        o.x = run;           run += v[k].x;
        o.y = run;           run += v[k].y;
        o.z = run;           run += v[k].z;
        o.w = run;           run += v[k].w;
        st4[k] = o;
        cc4[k] = make_int4(0, 0, 0, 0);    // restore replay invariant
    }
    if (tid == 0) g_cellStarts[s][CELLS] = NA;
}

// ---------------------------------------------------------------------------
// 3) scatter: atomic-free; pos = starts[cell] + rank.
__global__ __launch_bounds__(256) void scatter_kernel(
    const float* __restrict__ coord)
{
    int t = blockIdx.x * 256 + threadIdx.x;
    int s = t >> 13;
    int a = t & (NA - 1);
    float x = coord[3 * t], y = coord[3 * t + 1], z = coord[3 * t + 2];
    float q = fmaf(x, x, fmaf(y, y, z * z));
    int cr   = g_cellrank[t];
    int cell = cr & 0xFFFF;
    int rank = cr >> 16;
    int pos  = g_cellStarts[s][cell] + rank;
    g_pk[s][pos]   = make_float4(x, y, z, q);
    g_meta[s][pos] = g_chain[a];
}

// ---------------------------------------------------------------------------
// 4) search: forward half-stencil, thread per (atom, segment). Segments:
//    0..2: rows (z+1, y-1..y+1); 3: row (z, y+1); 4: own row tail j>k.
//    Forward cells have larger linear index and the own-cell scan starts at
//    k+1, so each unordered pair is visited exactly once with no id test.
//    fp32 predicate association identical to the accepted brute-force kernel.
//    Last-arriving block runs the fused finalize.
//    out layout: [ has (256 floats) | details (512 floats, (tot, rel)) ]
__global__ __launch_bounds__(256, 8) void search_kernel(float* __restrict__ out) {
    __shared__ int scnt[NC * NC];
    __shared__ int s_last;
    int tid = threadIdx.x;
    if (tid < NC * NC) scnt[tid] = 0;
    __syncthreads();

    int bx  = blockIdx.x;
    int seg = bx >> 7;                     // 0..4
    int t   = ((bx & 127) << 8) | tid;
    int s   = t >> 13;
    int k   = t & (NA - 1);

    float4 p  = g_pk[s][k];
    int    ci = g_meta[s][k];

    float m2x = -2.0f * p.x, m2y = -2.0f * p.y, m2z = -2.0f * p.z;
    float K   = p.w - THR2;

    int cx = cellco(p.x), cy = cellco(p.y), cz = cellco(p.z);
    int x0 = max(cx - 1, 0), x1 = min(cx + 1, GRID - 1);

    const int* st = g_cellStarts[s];
    int lo = 0, hi = 0;
    if (seg < 3) {
        int zz = cz + 1, yy = cy - 1 + seg;
        if (zz < GRID && yy >= 0 && yy < GRID) {
            int row = GRID * yy + GRIDXY * zz;
            lo = st[row + x0];
            hi = st[row + x1 + 1];
        }
    } else if (seg == 3) {
        int yy = cy + 1;
        if (yy < GRID) {
            int row = GRID * yy + GRIDXY * cz;
            lo = st[row + x0];
            hi = st[row + x1 + 1];
        }
    } else {
        int row = GRID * cy + GRIDXY * cz;
        lo = k + 1;                        // own-cell tail + forward-x cell
        hi = st[row + x1 + 1];
    }

    const float4* pk = g_pk[s];
    const int*    mt = g_meta[s];
    int bucket = ci * NC;

    int j = lo;
    for (; j + 1 < hi; j += 2) {
        float4 a = pk[j];
        float4 c = pk[j + 1];
        int ma = mt[j];
        int mb = mt[j + 1];
        float da = fmaf(m2z, a.z, fmaf(m2y, a.y, fmaf(m2x, a.x, a.w))) + K;
        float db = fmaf(m2z, c.z, fmaf(m2y, c.y, fmaf(m2x, c.x, c.w))) + K;
        if (da < 0.0f && ma != ci) atomicAdd(&scnt[bucket + ma], 1);
        if (db < 0.0f && mb != ci) atomicAdd(&scnt[bucket + mb], 1);
    }
    if (j < hi) {
        float4 a = pk[j];
        int ma = mt[j];
        float da = fmaf(m2z, a.z, fmaf(m2y, a.y, fmaf(m2x, a.x, a.w))) + K;
        if (da < 0.0f && ma != ci) atomicAdd(&scnt[bucket + ma], 1);
    }

    __syncthreads();
    if (tid < NC * NC) {
        int v = scnt[tid];
        if (v) atomicAdd(&g_counts[s * NC * NC + tid], v);
    }
    __threadfence();
    __syncthreads();
    if (tid == 0) {
        int r = atomicAdd(&g_sd, 1);
        s_last = (r == 5 * 128 - 1);
        if (s_last) g_sd = 0;              // reset for next replay
    }
    __syncthreads();
    if (!s_last) return;

    // ---- fused finalize (256 threads -> one (sample, a, b) each) ----
    {
        int fs = tid >> 6;
        int r  = tid & 63;
        int a  = r >> 3;
        int b  = r & 7;

        int tot_i = 0;
        if (a != b)
            tot_i = __ldcg(&g_counts[fs * NC * NC + a * NC + b]) +
                    __ldcg(&g_counts[fs * NC * NC + b * NC + a]);
        float tot = (float)tot_i;
        float mn  = (float)min(__ldcg(&g_npc[a]), __ldcg(&g_npc[b]));
        float rel = tot / mn;
        bool  has = (tot > 100.0f) || (rel > 0.5f);

        out[tid]                        = has ? 1.0f : 0.0f;
        out[NS * NC * NC + 2 * tid]     = tot;
        out[NS * NC * NC + 2 * tid + 1] = rel;

        __syncthreads();                   // all reads done
        g_counts[tid] = 0;                 // reset replay invariants
        if (tid < NC) g_npc[tid] = 0;
    }
}

// ---------------------------------------------------------------------------
extern "C" void kernel_launch(void* const* d_in, const int* in_sizes, int n_in,
                              void* d_out, int out_size) {
    const float* coord = (const float*)d_in[0];   // [S, N, 3] f32
    const int*   asym  = (const int*)  d_in[1];   // [N_TOKENS] i32
    const int*   a2t   = (const int*)  d_in[2];   // [N] i32
    float*       out   = (float*)d_out;

    hist_kernel   <<<(NS * NA) / 256, 256>>>(coord, asym, a2t);
    scan_kernel   <<<NS, 1024>>>();
    scatter_kernel<<<(NS * NA) / 256, 256>>>(coord);
    search_kernel <<<5 * 128, 256>>>(out);
}

// round 11
// speedup vs baseline: 2.0649x; 1.3856x over previous
#include <cuda_runtime.h>

#define NS      4
#define NA      8192
#define NC      8
#define THR2    1.21f
#define GRID    32
#define GRIDXY  (GRID * GRID)
#define CELLS   (GRID * GRID * GRID)     // 32768
#define ORIGIN  (-17.632f)
#define INV_H   (1.0f / 1.102f)          // h = 1.102 > 1.1 clash radius
#define NBLK    128                      // build grid: <= #SMs -> co-resident

// Device-global scratch. Replay invariants: g_counts, g_npc, g_cellCounts,
// g_sd, g_sync* are zero on entry (zero-init at load; consumers re-zero).
__device__ int g_counts[NS * NC * NC];
__device__ int g_npc[NC];
__device__ int g_sd;                     // search blocks done
__device__ int g_sync0, g_sync1, g_sync2;
__device__ int g_partial[NS * 32];       // per-chunk scan partials
__device__ int g_chain[NA];
__device__ __align__(16) int    g_cellCounts[NS][CELLS];
__device__ __align__(16) int    g_cellStarts[NS][CELLS + 4];
__device__ __align__(16) float4 g_pk[NS][NA];   // (x,y,z,q) cell-sorted
__device__ int    g_meta[NS][NA];               // chain of sorted atom

__device__ __forceinline__ int cellco(float v) {
    int c = __float2int_rd((v - ORIGIN) * INV_H);
    return min(GRID - 1, max(0, c));
}

// Grid barrier: valid because all NBLK blocks are co-resident (NBLK <= SMs).
// prev (if non-null) is reset by the LAST arriver: every block already passed
// prev's poll before arriving here, so the store cannot race a poll.
__device__ __forceinline__ void gsync(int* ctr, int* prev) {
    __threadfence();
    __syncthreads();
    if (threadIdx.x == 0) {
        int r = atomicAdd(ctr, 1);
        if (prev && r == NBLK - 1) *prev = 0;
        while (*(volatile int*)ctr < NBLK) __nanosleep(32);
    }
    __syncthreads();
    __threadfence();
}

// ---------------------------------------------------------------------------
// build: hist -> scan -> scatter in ONE persistent kernel (2 grid barriers +
// 1 inside the scan). One thread per (sample, atom); cell/rank/coords stay in
// registers across phases.
__global__ __launch_bounds__(256) void build_kernel(
    const float* __restrict__ coord,
    const int*   __restrict__ asym,
    const int*   __restrict__ a2t)
{
    __shared__ int s_w[8];
    __shared__ int s_off;

    int tid = threadIdx.x;
    int t   = blockIdx.x * 256 + tid;    // 0 .. NS*NA-1 (exactly grid size)
    int s   = t >> 13;
    int a   = t & (NA - 1);

    // ---- P1: histogram (rank = atomic return), chain map + npc (t < NA) ---
    float x = coord[3 * t], y = coord[3 * t + 1], z = coord[3 * t + 2];
    float q = fmaf(x, x, fmaf(y, y, z * z));
    int cell = cellco(x) + GRID * cellco(y) + GRIDXY * cellco(z);
    int rank = atomicAdd(&g_cellCounts[s][cell], 1);
    if (t < NA) {
        int ch = asym[a2t[t]];
        g_chain[t] = ch;
        atomicAdd(&g_npc[ch], 1);
    }

    gsync(&g_sync0, 0);

    // ---- P2a: local scan of this block's 1024-cell chunk ------------------
    int sb = blockIdx.x >> 5;            // sample of this chunk
    int ch = blockIdx.x & 31;            // chunk within sample
    int base = ch * 1024 + tid * 4;
    int4 v = *(const int4*)(g_cellCounts[sb] + base);
    int sum = v.x + v.y + v.z + v.w;

    int lane = tid & 31, wid = tid >> 5;
    int inc = sum;
#pragma unroll
    for (int d = 1; d < 32; d <<= 1) {
        int u = __shfl_up_sync(0xFFFFFFFF, inc, d);
        if (lane >= d) inc += u;
    }
    if (lane == 31) s_w[wid] = inc;
    __syncthreads();
    if (tid < 8) {
        int wv = s_w[tid];
        int wi = wv;
#pragma unroll
        for (int d = 1; d < 8; d <<= 1) {
            int u = __shfl_up_sync(0xFF, wi, d);
            if (tid >= d) wi += u;
        }
        s_w[tid] = wi - wv;              // exclusive warp offsets
        if (tid == 7) g_partial[sb * 32 + ch] = wi;   // block total
    }
    __syncthreads();
    int run = s_w[wid] + (inc - sum);    // exclusive local start
    *(int4*)(g_cellCounts[sb] + base) = make_int4(0, 0, 0, 0);  // invariant

    gsync(&g_sync1, &g_sync0);

    // ---- P2b: add cross-chunk offset, store starts -------------------------
    if (tid < 32) {
        int pv = (tid < ch) ? g_partial[sb * 32 + tid] : 0;
#pragma unroll
        for (int d = 16; d > 0; d >>= 1)
            pv += __shfl_down_sync(0xFFFFFFFF, pv, d);
        if (tid == 0) s_off = pv;
    }
    __syncthreads();
    int off = s_off;
    int4 o;
    o.x = run + off;
    o.y = o.x + v.x;
    o.z = o.y + v.y;
    o.w = o.z + v.z;
    *(int4*)(g_cellStarts[sb] + base) = o;
    if (ch == 31 && tid == 255) g_cellStarts[sb][CELLS] = NA;

    gsync(&g_sync2, &g_sync1);

    // ---- P3: scatter from registers ----------------------------------------
    int pos = g_cellStarts[s][cell] + rank;
    g_pk[s][pos]   = make_float4(x, y, z, q);
    g_meta[s][pos] = g_chain[a];
}

// ---------------------------------------------------------------------------
// search: forward half-stencil, thread per (atom, segment). Segments:
//    0..2: rows (z+1, y-1..y+1); 3: row (z, y+1); 4: own row tail j>k.
// Forward cells have larger linear index and the own-cell scan starts at k+1,
// so each unordered pair is visited exactly once with no id test. fp32
// predicate association identical to the accepted brute-force kernel.
// Last-arriving block runs the fused finalize and resets replay counters.
// out layout: [ has (256 floats) | details (512 floats, (tot, rel)) ]
__global__ __launch_bounds__(256, 8) void search_kernel(float* __restrict__ out) {
    __shared__ int scnt[NC * NC];
    __shared__ int s_last;
    int tid = threadIdx.x;
    if (tid < NC * NC) scnt[tid] = 0;
    __syncthreads();

    int bx  = blockIdx.x;
    int seg = bx >> 7;                     // 0..4
    int t   = ((bx & 127) << 8) | tid;
    int s   = t >> 13;
    int k   = t & (NA - 1);

    float4 p  = g_pk[s][k];
    int    ci = g_meta[s][k];

    float m2x = -2.0f * p.x, m2y = -2.0f * p.y, m2z = -2.0f * p.z;
    float K   = p.w - THR2;

    int cx = cellco(p.x), cy = cellco(p.y), cz = cellco(p.z);
    int x0 = max(cx - 1, 0), x1 = min(cx + 1, GRID - 1);

    const int* st = g_cellStarts[s];
    int lo = 0, hi = 0;
    if (seg < 3) {
        int zz = cz + 1, yy = cy - 1 + seg;
        if (zz < GRID && yy >= 0 && yy < GRID) {
            int row = GRID * yy + GRIDXY * zz;
            lo = st[row + x0];
            hi = st[row + x1 + 1];
        }
    } else if (seg == 3) {
        int yy = cy + 1;
        if (yy < GRID) {
            int row = GRID * yy + GRIDXY * cz;
            lo = st[row + x0];
            hi = st[row + x1 + 1];
        }
    } else {
        int row = GRID * cy + GRIDXY * cz;
        lo = k + 1;                        // own-cell tail + forward-x cell
        hi = st[row + x1 + 1];
    }

    const float4* pk = g_pk[s];
    const int*    mt = g_meta[s];
    int bucket = ci * NC;

    int j = lo;
    for (; j + 1 < hi; j += 2) {
        float4 a = pk[j];
        float4 c = pk[j + 1];
        int ma = mt[j];
        int mb = mt[j + 1];
        float da = fmaf(m2z, a.z, fmaf(m2y, a.y, fmaf(m2x, a.x, a.w))) + K;
        float db = fmaf(m2z, c.z, fmaf(m2y, c.y, fmaf(m2x, c.x, c.w))) + K;
        if (da < 0.0f && ma != ci) atomicAdd(&scnt[bucket + ma], 1);
        if (db < 0.0f && mb != ci) atomicAdd(&scnt[bucket + mb], 1);
    }
    if (j < hi) {
        float4 a = pk[j];
        int ma = mt[j];
        float da = fmaf(m2z, a.z, fmaf(m2y, a.y, fmaf(m2x, a.x, a.w))) + K;
        if (da < 0.0f && ma != ci) atomicAdd(&scnt[bucket + ma], 1);
    }

    __syncthreads();
    if (tid < NC * NC) {
        int v = scnt[tid];
        if (v) atomicAdd(&g_counts[s * NC * NC + tid], v);
    }
    __threadfence();
    __syncthreads();
    if (tid == 0) {
        int r = atomicAdd(&g_sd, 1);
        s_last = (r == 5 * 128 - 1);
        if (s_last) { g_sd = 0; g_sync2 = 0; }   // reset replay counters
    }
    __syncthreads();
    if (!s_last) return;

    // ---- fused finalize (256 threads -> one (sample, a, b) each) ----
    {
        int fs = tid >> 6;
        int r  = tid & 63;
        int a  = r >> 3;
        int b  = r & 7;

        int tot_i = 0;
        if (a != b)
            tot_i = __ldcg(&g_counts[fs * NC * NC + a * NC + b]) +
                    __ldcg(&g_counts[fs * NC * NC + b * NC + a]);
        float tot = (float)tot_i;
        float mn  = (float)min(__ldcg(&g_npc[a]), __ldcg(&g_npc[b]));
        float rel = tot / mn;
        bool  has = (tot > 100.0f) || (rel > 0.5f);

        out[tid]                        = has ? 1.0f : 0.0f;
        out[NS * NC * NC + 2 * tid]     = tot;
        out[NS * NC * NC + 2 * tid + 1] = rel;

        __syncthreads();                   // all reads done
        g_counts[tid] = 0;                 // reset replay invariants
        if (tid < NC) g_npc[tid] = 0;
    }
}

// ---------------------------------------------------------------------------
extern "C" void kernel_launch(void* const* d_in, const int* in_sizes, int n_in,
                              void* d_out, int out_size) {
    const float* coord = (const float*)d_in[0];   // [S, N, 3] f32
    const int*   asym  = (const int*)  d_in[1];   // [N_TOKENS] i32
    const int*   a2t   = (const int*)  d_in[2];   // [N] i32
    float*       out   = (float*)d_out;

    build_kernel <<<NBLK, 256>>>(coord, asym, a2t);
    search_kernel<<<5 * 128, 256>>>(out);
}